// round 1
// baseline (speedup 1.0000x reference)
#include <cuda_runtime.h>

// AdaLoRALinear: out = x @ (W + scaling * (B * sigma_masked) @ A)^T
// x: [4,2048,4096] f32 -> M=8192, K=4096
// W: [4096,4096] (out, in) row-major -> N=4096, K-contiguous
// lora_A: [16,4096], lora_B: [4096,16], sigma: [16]
//
// Plan: (1) fold rank-16 delta into W' (device scratch), (2) SGEMM NT.

#define D_DIM 4096
#define R_DIM 16
#define M_DIM 8192
#define SCALING 1.0f       // 16.0 / 16
#define THRESH  0.01f

// 64 MB scratch for the folded weight (allocation-free rule: __device__ global).
__device__ float g_Wp[(size_t)D_DIM * D_DIM];

// ---------------------------------------------------------------------------
// Kernel 1: W' = W + SCALING * (B * sigma_masked) @ A
// grid: (D/256, D), block 256. o = blockIdx.y (out dim), i along x (in dim).
// ---------------------------------------------------------------------------
__global__ void fold_delta_kernel(const float* __restrict__ W,
                                  const float* __restrict__ A,
                                  const float* __restrict__ B,
                                  const float* __restrict__ sigma) {
    __shared__ float bsig[R_DIM];
    const int o = blockIdx.y;
    const int i = blockIdx.x * blockDim.x + threadIdx.x;

    if (threadIdx.x < R_DIM) {
        float s = sigma[threadIdx.x];
        s = (fabsf(s) >= THRESH) ? s : 0.0f;
        bsig[threadIdx.x] = B[o * R_DIM + threadIdx.x] * s * SCALING;
    }
    __syncthreads();

    float acc = 0.0f;
#pragma unroll
    for (int r = 0; r < R_DIM; r++)
        acc = fmaf(bsig[r], A[(size_t)r * D_DIM + i], acc);

    const size_t idx = (size_t)o * D_DIM + i;
    g_Wp[idx] = W[idx] + acc;
}

// ---------------------------------------------------------------------------
// Kernel 2: SGEMM  out[M,N] = X[M,K] * Wp[N,K]^T   (both K-contiguous, "NT")
// Tiles: BM=128, BN=128, BK=16. 256 threads (16x16), 8x8 per thread.
// ---------------------------------------------------------------------------
#define BM 128
#define BN 128
#define BK 16
#define TM 8
#define TN 8

__global__ __launch_bounds__(256, 2)
void sgemm_nt_kernel(const float* __restrict__ X,
                     float* __restrict__ out) {
    __shared__ float As[BK][BM];   // transposed: As[k][m]
    __shared__ float Bs[BK][BN];   // transposed: Bs[k][n]

    const int K = D_DIM;
    const int Ncol = D_DIM;

    const int tid = threadIdx.x;
    const int tx = tid & 15;        // 0..15 -> n sub-tile
    const int ty = tid >> 4;        // 0..15 -> m sub-tile

    const size_t mBase = (size_t)blockIdx.y * BM;
    const size_t nBase = (size_t)blockIdx.x * BN;

    const float* Xblk = X + mBase * K;
    const float* Wblk = g_Wp + nBase * K;

    float acc[TM][TN];
#pragma unroll
    for (int i = 0; i < TM; i++)
#pragma unroll
        for (int j = 0; j < TN; j++)
            acc[i][j] = 0.0f;

    for (int kt = 0; kt < K; kt += BK) {
        // Each tile is 128 rows x 16 k = 512 float4; 256 threads -> 2 each.
#pragma unroll
        for (int l2 = 0; l2 < 2; l2++) {
            const int l   = tid * 2 + l2;
            const int row = l >> 2;            // 0..127
            const int c4  = (l & 3) << 2;      // k offset within tile: 0,4,8,12

            float4 va = *reinterpret_cast<const float4*>(
                Xblk + (size_t)row * K + kt + c4);
            As[c4 + 0][row] = va.x;
            As[c4 + 1][row] = va.y;
            As[c4 + 2][row] = va.z;
            As[c4 + 3][row] = va.w;

            float4 vb = *reinterpret_cast<const float4*>(
                Wblk + (size_t)row * K + kt + c4);
            Bs[c4 + 0][row] = vb.x;
            Bs[c4 + 1][row] = vb.y;
            Bs[c4 + 2][row] = vb.z;
            Bs[c4 + 3][row] = vb.w;
        }
        __syncthreads();

#pragma unroll
        for (int k = 0; k < BK; k++) {
            float a[TM], b[TN];
#pragma unroll
            for (int i = 0; i < TM; i++) a[i] = As[k][ty * TM + i];
#pragma unroll
            for (int j = 0; j < TN; j++) b[j] = Bs[k][tx * TN + j];
#pragma unroll
            for (int i = 0; i < TM; i++)
#pragma unroll
                for (int j = 0; j < TN; j++)
                    acc[i][j] = fmaf(a[i], b[j], acc[i][j]);
        }
        __syncthreads();
    }

    // Store 8x8 per thread as 2x float4 per row.
#pragma unroll
    for (int i = 0; i < TM; i++) {
        const size_t row = mBase + (size_t)ty * TM + i;
        float4* po = reinterpret_cast<float4*>(
            out + row * Ncol + nBase + (size_t)tx * TN);
        po[0] = make_float4(acc[i][0], acc[i][1], acc[i][2], acc[i][3]);
        po[1] = make_float4(acc[i][4], acc[i][5], acc[i][6], acc[i][7]);
    }
}

// ---------------------------------------------------------------------------
// Launch
// ---------------------------------------------------------------------------
extern "C" void kernel_launch(void* const* d_in, const int* in_sizes, int n_in,
                              void* d_out, int out_size) {
    const float* x     = (const float*)d_in[0];  // [4,2048,4096]
    const float* W     = (const float*)d_in[1];  // [4096,4096]
    const float* lA    = (const float*)d_in[2];  // [16,4096]
    const float* lB    = (const float*)d_in[3];  // [4096,16]
    const float* sigma = (const float*)d_in[4];  // [16]
    float* out = (float*)d_out;

    (void)in_sizes; (void)n_in; (void)out_size;

    dim3 gFold(D_DIM / 256, D_DIM);
    fold_delta_kernel<<<gFold, 256>>>(W, lA, lB, sigma);

    dim3 gGemm(D_DIM / BN, M_DIM / BM);
    sgemm_nt_kernel<<<gGemm, 256>>>(x, out);
}

// round 3
// speedup vs baseline: 3.3789x; 3.3789x over previous
#include <cuda_runtime.h>
#include <cuda_bf16.h>
#include <cstdint>

// AdaLoRALinear: out[8192,4096] = x[8192,4096] @ (W + (B*sigma_m)@A)^T
// bf16x3 emulated-fp32 GEMM on mma.sync (HMMA) — tcgen05 unavailable at sm_103 target.

#define D_DIM 4096
#define R_DIM 16
#define M_DIM 8192
#define SCALING 1.0f
#define THRESH  0.01f

#define BM 128
#define BN 128
#define BK 64                  // 64 bf16 = 128B row (SW128 atom)
#define KITERS (D_DIM / BK)    // 64
#define STAGES 3

// Device scratch (allocation-free rule: __device__ globals)
__device__ __nv_bfloat16 g_xh[(size_t)M_DIM * D_DIM];
__device__ __nv_bfloat16 g_xl[(size_t)M_DIM * D_DIM];
__device__ __nv_bfloat16 g_wh[(size_t)D_DIM * D_DIM];
__device__ __nv_bfloat16 g_wl[(size_t)D_DIM * D_DIM];

// ---------------------------------------------------------------------------
// helpers
// ---------------------------------------------------------------------------
__device__ __forceinline__ uint32_t smem_u32(const void* p) {
    uint32_t a;
    asm("{ .reg .u64 t; cvta.to.shared.u64 t, %1; cvt.u32.u64 %0, t; }"
        : "=r"(a) : "l"(p));
    return a;
}
__device__ __forceinline__ uint32_t swz128(uint32_t off) {
    return off ^ ((off >> 3) & 0x70);
}
__device__ __forceinline__ void cp16(uint32_t smem, const void* g) {
    asm volatile("cp.async.cg.shared.global [%0], [%1], 16;\n"
                 :: "r"(smem), "l"(g) : "memory");
}
__device__ __forceinline__ void cp_commit() {
    asm volatile("cp.async.commit_group;\n" ::: "memory");
}
__device__ __forceinline__ void cp_wait1() {
    asm volatile("cp.async.wait_group 1;\n" ::: "memory");
}
__device__ __forceinline__ void ldsm4(uint32_t* r, uint32_t addr) {
    asm volatile("ldmatrix.sync.aligned.m8n8.x4.shared.b16 {%0,%1,%2,%3}, [%4];"
                 : "=r"(r[0]), "=r"(r[1]), "=r"(r[2]), "=r"(r[3]) : "r"(addr));
}
__device__ __forceinline__ void mma_bf16(float* d, const uint32_t* a,
                                         const uint32_t* b) {
    asm volatile(
        "mma.sync.aligned.m16n8k16.row.col.f32.bf16.bf16.f32 "
        "{%0,%1,%2,%3}, {%4,%5,%6,%7}, {%8,%9}, {%0,%1,%2,%3};"
        : "+f"(d[0]), "+f"(d[1]), "+f"(d[2]), "+f"(d[3])
        : "r"(a[0]), "r"(a[1]), "r"(a[2]), "r"(a[3]), "r"(b[0]), "r"(b[1]));
}

// ---------------------------------------------------------------------------
// Prep kernel 1: W' = W + (B*sigma_m)@A, split hi/lo bf16
// ---------------------------------------------------------------------------
__global__ void fold_w_kernel(const float* __restrict__ W,
                              const float* __restrict__ A,
                              const float* __restrict__ B,
                              const float* __restrict__ sigma) {
    __shared__ float bsig[R_DIM];
    const int o = blockIdx.y;
    const int i = blockIdx.x * blockDim.x + threadIdx.x;
    if (threadIdx.x < R_DIM) {
        float s = sigma[threadIdx.x];
        s = (fabsf(s) >= THRESH) ? s : 0.0f;
        bsig[threadIdx.x] = B[o * R_DIM + threadIdx.x] * s * SCALING;
    }
    __syncthreads();
    float acc = 0.0f;
#pragma unroll
    for (int r = 0; r < R_DIM; r++)
        acc = fmaf(bsig[r], A[(size_t)r * D_DIM + i], acc);
    const size_t idx = (size_t)o * D_DIM + i;
    float wp = W[idx] + acc;
    __nv_bfloat16 h = __float2bfloat16(wp);
    __nv_bfloat16 l = __float2bfloat16(wp - __bfloat162float(h));
    g_wh[idx] = h;
    g_wl[idx] = l;
}

// ---------------------------------------------------------------------------
// Prep kernel 2: split x into hi/lo bf16
// ---------------------------------------------------------------------------
__global__ void split_x_kernel(const float* __restrict__ x) {
    const size_t idx = (size_t)blockIdx.x * blockDim.x + threadIdx.x;
    const float4 v = reinterpret_cast<const float4*>(x)[idx];
    __nv_bfloat16 h[4], l[4];
    float vv[4] = {v.x, v.y, v.z, v.w};
#pragma unroll
    for (int j = 0; j < 4; j++) {
        h[j] = __float2bfloat16(vv[j]);
        l[j] = __float2bfloat16(vv[j] - __bfloat162float(h[j]));
    }
    *reinterpret_cast<uint2*>(&g_xh[idx * 4]) = *reinterpret_cast<uint2*>(h);
    *reinterpret_cast<uint2*>(&g_xl[idx * 4]) = *reinterpret_cast<uint2*>(l);
}

// ---------------------------------------------------------------------------
// GEMM: CTA 128x128, 8 warps (2m x 4n), warp tile 64x32, BK=64, 3-stage pipe.
// Stage layout (64 KB): Ah(16K) Al(16K) Bh(16K) Bl(16K); SW128-swizzled rows.
// ---------------------------------------------------------------------------
#define STAGE_BYTES 65536
#define OFF_AH 0
#define OFF_AL 16384
#define OFF_BH 32768
#define OFF_BL 49152
#define SMEM_BYTES (STAGES * STAGE_BYTES + 128)

__device__ __forceinline__ void load_stage(uint32_t base, size_t mBase,
                                           size_t nBase, int kt, int tid) {
#pragma unroll
    for (int i = 0; i < 4; i++) {
        const int u = tid + 256 * i;
        const int row = u >> 3, kc = u & 7;
        const uint32_t so = swz128(row * 128 + kc * 16);
        const size_t ga = ((mBase + row) << 12) + kt + kc * 8;
        const size_t gb = ((nBase + row) << 12) + kt + kc * 8;
        cp16(base + OFF_AH + so, g_xh + ga);
        cp16(base + OFF_AL + so, g_xl + ga);
        cp16(base + OFF_BH + so, g_wh + gb);
        cp16(base + OFF_BL + so, g_wl + gb);
    }
}

__global__ __launch_bounds__(256, 1)
void gemm_mma_kernel(float* __restrict__ out) {
    extern __shared__ char smem_raw[];
    const uint32_t tiles = (smem_u32(smem_raw) + 127u) & ~127u;

    const int tid = threadIdx.x;
    const int lane = tid & 31;
    const int w = tid >> 5;
    const int wm = w >> 2;        // 0..1
    const int wn = w & 3;         // 0..3
    const size_t mBase = (size_t)blockIdx.y * BM;
    const size_t nBase = (size_t)blockIdx.x * BN;

    float d[4][4][4];
#pragma unroll
    for (int i = 0; i < 4; i++)
#pragma unroll
        for (int j = 0; j < 4; j++)
#pragma unroll
            for (int k = 0; k < 4; k++) d[i][j][k] = 0.0f;

    // per-lane ldmatrix row/col components (within tile)
    const int arow = wm * 64 + (lane & 15);     // + mi*16
    const int acol = (lane >> 4);               // + k16*2
    const int brow = wn * 32 + (lane & 7) + ((lane >> 4) << 3);  // + j*16
    const int bcol = ((lane >> 3) & 1);         // + k16*2

    // prologue: stages 0,1
    load_stage(tiles, mBase, nBase, 0, tid);
    cp_commit();
    load_stage(tiles + STAGE_BYTES, mBase, nBase, BK, tid);
    cp_commit();

    for (int it = 0; it < KITERS; it++) {
        const uint32_t stg = tiles + (it % 3) * STAGE_BYTES;

        cp_wait1();
        __syncthreads();

        if (it + 2 < KITERS)
            load_stage(tiles + ((it + 2) % 3) * STAGE_BYTES,
                       mBase, nBase, (it + 2) * BK, tid);
        cp_commit();

#pragma unroll
        for (int k16 = 0; k16 < 4; k16++) {
            uint32_t aH[4][4], aL[4][4], bH[4][2], bL[4][2];
#pragma unroll
            for (int mi = 0; mi < 4; mi++) {
                const uint32_t off =
                    swz128((arow + mi * 16) * 128 + (acol + k16 * 2) * 16);
                ldsm4(aH[mi], stg + OFF_AH + off);
                ldsm4(aL[mi], stg + OFF_AL + off);
            }
#pragma unroll
            for (int j = 0; j < 2; j++) {
                uint32_t q[4];
                const uint32_t off =
                    swz128((brow + j * 16) * 128 + (bcol + k16 * 2) * 16);
                ldsm4(q, stg + OFF_BH + off);
                bH[2 * j][0] = q[0]; bH[2 * j][1] = q[1];
                bH[2 * j + 1][0] = q[2]; bH[2 * j + 1][1] = q[3];
                ldsm4(q, stg + OFF_BL + off);
                bL[2 * j][0] = q[0]; bL[2 * j][1] = q[1];
                bL[2 * j + 1][0] = q[2]; bL[2 * j + 1][1] = q[3];
            }
#pragma unroll
            for (int mi = 0; mi < 4; mi++)
#pragma unroll
                for (int nj = 0; nj < 4; nj++) {
                    mma_bf16(d[mi][nj], aH[mi], bH[nj]);
                    mma_bf16(d[mi][nj], aH[mi], bL[nj]);
                    mma_bf16(d[mi][nj], aL[mi], bH[nj]);
                }
        }
    }

    // epilogue: c0,c1 -> row (lane>>2), cols (lane&3)*2; c2,c3 -> row+8
#pragma unroll
    for (int mi = 0; mi < 4; mi++) {
        const size_t grow = mBase + wm * 64 + mi * 16 + (lane >> 2);
#pragma unroll
        for (int nj = 0; nj < 4; nj++) {
            const size_t gcol = nBase + wn * 32 + nj * 8 + (lane & 3) * 2;
            *reinterpret_cast<float2*>(out + grow * D_DIM + gcol) =
                make_float2(d[mi][nj][0], d[mi][nj][1]);
            *reinterpret_cast<float2*>(out + (grow + 8) * D_DIM + gcol) =
                make_float2(d[mi][nj][2], d[mi][nj][3]);
        }
    }
}

// ---------------------------------------------------------------------------
// Launch
// ---------------------------------------------------------------------------
extern "C" void kernel_launch(void* const* d_in, const int* in_sizes, int n_in,
                              void* d_out, int out_size) {
    const float* x     = (const float*)d_in[0];
    const float* W     = (const float*)d_in[1];
    const float* lA    = (const float*)d_in[2];
    const float* lB    = (const float*)d_in[3];
    const float* sigma = (const float*)d_in[4];
    float* out = (float*)d_out;
    (void)in_sizes; (void)n_in; (void)out_size;

    dim3 gF(D_DIM / 256, D_DIM);
    fold_w_kernel<<<gF, 256>>>(W, lA, lB, sigma);

    const size_t nx4 = (size_t)M_DIM * D_DIM / 4;
    split_x_kernel<<<(unsigned)(nx4 / 256), 256>>>(x);

    cudaFuncSetAttribute(gemm_mma_kernel,
                         cudaFuncAttributeMaxDynamicSharedMemorySize, SMEM_BYTES);
    dim3 gG(D_DIM / BN, M_DIM / BM);
    gemm_mma_kernel<<<gG, 256, SMEM_BYTES>>>(out);
}

// round 4
// speedup vs baseline: 3.5345x; 1.0460x over previous
#include <cuda_runtime.h>
#include <cuda_bf16.h>
#include <cstdint>

// AdaLoRALinear: out[8192,4096] = x[8192,4096] @ (W + (B*sigma_m)@A)^T
// bf16x3 emulated-fp32 GEMM on mma.sync. CTA 128x256, warp 64x64, 2-stage pipe.

#define D_DIM 4096
#define R_DIM 16
#define M_DIM 8192
#define SCALING 1.0f
#define THRESH  0.01f

#define BM 128
#define BN 256
#define BK 64                  // 64 bf16 = 128B row (SW128 atom)
#define KITERS (D_DIM / BK)    // 64

__device__ __nv_bfloat16 g_xh[(size_t)M_DIM * D_DIM];
__device__ __nv_bfloat16 g_xl[(size_t)M_DIM * D_DIM];
__device__ __nv_bfloat16 g_wh[(size_t)D_DIM * D_DIM];
__device__ __nv_bfloat16 g_wl[(size_t)D_DIM * D_DIM];

// ---------------------------------------------------------------------------
// helpers
// ---------------------------------------------------------------------------
__device__ __forceinline__ uint32_t smem_u32(const void* p) {
    uint32_t a;
    asm("{ .reg .u64 t; cvta.to.shared.u64 t, %1; cvt.u32.u64 %0, t; }"
        : "=r"(a) : "l"(p));
    return a;
}
__device__ __forceinline__ uint32_t swz128(uint32_t off) {
    return off ^ ((off >> 3) & 0x70);
}
__device__ __forceinline__ void cp16(uint32_t smem, const void* g) {
    asm volatile("cp.async.cg.shared.global [%0], [%1], 16;\n"
                 :: "r"(smem), "l"(g) : "memory");
}
__device__ __forceinline__ void cp_commit() {
    asm volatile("cp.async.commit_group;\n" ::: "memory");
}
__device__ __forceinline__ void cp_wait1() {
    asm volatile("cp.async.wait_group 1;\n" ::: "memory");
}
__device__ __forceinline__ void ldsm4(uint32_t* r, uint32_t addr) {
    asm volatile("ldmatrix.sync.aligned.m8n8.x4.shared.b16 {%0,%1,%2,%3}, [%4];"
                 : "=r"(r[0]), "=r"(r[1]), "=r"(r[2]), "=r"(r[3]) : "r"(addr));
}
__device__ __forceinline__ void mma_bf16(float* d, const uint32_t* a,
                                         const uint32_t* b) {
    asm volatile(
        "mma.sync.aligned.m16n8k16.row.col.f32.bf16.bf16.f32 "
        "{%0,%1,%2,%3}, {%4,%5,%6,%7}, {%8,%9}, {%0,%1,%2,%3};"
        : "+f"(d[0]), "+f"(d[1]), "+f"(d[2]), "+f"(d[3])
        : "r"(a[0]), "r"(a[1]), "r"(a[2]), "r"(a[3]), "r"(b[0]), "r"(b[1]));
}

// ---------------------------------------------------------------------------
// Prep 1: W' = W + (B*sigma_m)@A, split hi/lo bf16. Vectorized x4.
// grid (D/1024, D), block 256: block handles 1024 consecutive i of one o-row.
// ---------------------------------------------------------------------------
__global__ void fold_w_kernel(const float* __restrict__ W,
                              const float* __restrict__ A,
                              const float* __restrict__ B,
                              const float* __restrict__ sigma) {
    __shared__ float bsig[R_DIM];
    const int o = blockIdx.y;
    const int i = (blockIdx.x * blockDim.x + threadIdx.x) * 4;
    if (threadIdx.x < R_DIM) {
        float s = sigma[threadIdx.x];
        s = (fabsf(s) >= THRESH) ? s : 0.0f;
        bsig[threadIdx.x] = B[o * R_DIM + threadIdx.x] * s * SCALING;
    }
    __syncthreads();

    const size_t idx = (size_t)o * D_DIM + i;
    float4 w4 = *reinterpret_cast<const float4*>(W + idx);
    float acc[4] = {w4.x, w4.y, w4.z, w4.w};
#pragma unroll
    for (int r = 0; r < R_DIM; r++) {
        const float4 a4 = *reinterpret_cast<const float4*>(A + (size_t)r * D_DIM + i);
        const float b = bsig[r];
        acc[0] = fmaf(b, a4.x, acc[0]);
        acc[1] = fmaf(b, a4.y, acc[1]);
        acc[2] = fmaf(b, a4.z, acc[2]);
        acc[3] = fmaf(b, a4.w, acc[3]);
    }
    __nv_bfloat16 h[4], l[4];
#pragma unroll
    for (int j = 0; j < 4; j++) {
        h[j] = __float2bfloat16(acc[j]);
        l[j] = __float2bfloat16(acc[j] - __bfloat162float(h[j]));
    }
    *reinterpret_cast<uint2*>(&g_wh[idx]) = *reinterpret_cast<uint2*>(h);
    *reinterpret_cast<uint2*>(&g_wl[idx]) = *reinterpret_cast<uint2*>(l);
}

// ---------------------------------------------------------------------------
// Prep 2: split x into hi/lo bf16
// ---------------------------------------------------------------------------
__global__ void split_x_kernel(const float* __restrict__ x) {
    const size_t idx = (size_t)blockIdx.x * blockDim.x + threadIdx.x;
    const float4 v = reinterpret_cast<const float4*>(x)[idx];
    __nv_bfloat16 h[4], l[4];
    float vv[4] = {v.x, v.y, v.z, v.w};
#pragma unroll
    for (int j = 0; j < 4; j++) {
        h[j] = __float2bfloat16(vv[j]);
        l[j] = __float2bfloat16(vv[j] - __bfloat162float(h[j]));
    }
    *reinterpret_cast<uint2*>(&g_xh[idx * 4]) = *reinterpret_cast<uint2*>(h);
    *reinterpret_cast<uint2*>(&g_xl[idx * 4]) = *reinterpret_cast<uint2*>(l);
}

// ---------------------------------------------------------------------------
// GEMM: CTA 128x256, 8 warps (2m x 4n), warp tile 64x64, BK=64, 2-stage pipe.
// Stage (96 KB): Ah(16K) Al(16K) Bh(32K) Bl(32K), SW128 rows.
// ---------------------------------------------------------------------------
#define STAGE_BYTES 98304
#define OFF_AH 0
#define OFF_AL 16384
#define OFF_BH 32768
#define OFF_BL 65536
#define SMEM_BYTES (2 * STAGE_BYTES + 128)

__device__ __forceinline__ void load_stage(uint32_t base, size_t mBase,
                                           size_t nBase, int kt, int tid) {
#pragma unroll
    for (int i = 0; i < 4; i++) {   // A hi/lo: 128 rows x 8 units
        const int u = tid + 256 * i;
        const int row = u >> 3, kc = u & 7;
        const uint32_t so = swz128(row * 128 + kc * 16);
        const size_t ga = ((mBase + row) << 12) + kt + kc * 8;
        cp16(base + OFF_AH + so, g_xh + ga);
        cp16(base + OFF_AL + so, g_xl + ga);
    }
#pragma unroll
    for (int i = 0; i < 8; i++) {   // B hi/lo: 256 rows x 8 units
        const int u = tid + 256 * i;
        const int row = u >> 3, kc = u & 7;
        const uint32_t so = swz128(row * 128 + kc * 16);
        const size_t gb = ((nBase + row) << 12) + kt + kc * 8;
        cp16(base + OFF_BH + so, g_wh + gb);
        cp16(base + OFF_BL + so, g_wl + gb);
    }
}

__global__ __launch_bounds__(256, 1)
void gemm_mma_kernel(float* __restrict__ out) {
    extern __shared__ char smem_raw[];
    const uint32_t tiles = (smem_u32(smem_raw) + 127u) & ~127u;

    const int tid = threadIdx.x;
    const int lane = tid & 31;
    const int w = tid >> 5;
    const int wm = w >> 2;        // 0..1 -> M half
    const int wn = w & 3;         // 0..3 -> N quarter
    const size_t mBase = (size_t)blockIdx.y * BM;
    const size_t nBase = (size_t)blockIdx.x * BN;

    float d[4][8][4];
#pragma unroll
    for (int i = 0; i < 4; i++)
#pragma unroll
        for (int j = 0; j < 8; j++)
#pragma unroll
            for (int k = 0; k < 4; k++) d[i][j][k] = 0.0f;

    const int arow = wm * 64 + (lane & 15);
    const int acol = (lane >> 4);
    const int brow = wn * 64 + (lane & 7) + ((lane >> 4) << 3);
    const int bcol = ((lane >> 3) & 1);

    load_stage(tiles, mBase, nBase, 0, tid);
    cp_commit();
    load_stage(tiles + STAGE_BYTES, mBase, nBase, BK, tid);
    cp_commit();

    for (int it = 0; it < KITERS; it++) {
        const uint32_t stg = tiles + (it & 1) * STAGE_BYTES;

        cp_wait1();
        __syncthreads();

#pragma unroll
        for (int k16 = 0; k16 < 4; k16++) {
            uint32_t aH[4][4], aL[4][4], bH[8][2], bL[8][2];
#pragma unroll
            for (int mi = 0; mi < 4; mi++) {
                const uint32_t off =
                    swz128((arow + mi * 16) * 128 + (acol + k16 * 2) * 16);
                ldsm4(aH[mi], stg + OFF_AH + off);
                ldsm4(aL[mi], stg + OFF_AL + off);
            }
#pragma unroll
            for (int j = 0; j < 4; j++) {
                uint32_t q[4];
                const uint32_t off =
                    swz128((brow + j * 16) * 128 + (bcol + k16 * 2) * 16);
                ldsm4(q, stg + OFF_BH + off);
                bH[2 * j][0] = q[0]; bH[2 * j][1] = q[1];
                bH[2 * j + 1][0] = q[2]; bH[2 * j + 1][1] = q[3];
                ldsm4(q, stg + OFF_BL + off);
                bL[2 * j][0] = q[0]; bL[2 * j][1] = q[1];
                bL[2 * j + 1][0] = q[2]; bL[2 * j + 1][1] = q[3];
            }
            // product-outer order: 32 independent accumulators between reuses
#pragma unroll
            for (int mi = 0; mi < 4; mi++)
#pragma unroll
                for (int nj = 0; nj < 8; nj++)
                    mma_bf16(d[mi][nj], aH[mi], bH[nj]);
#pragma unroll
            for (int mi = 0; mi < 4; mi++)
#pragma unroll
                for (int nj = 0; nj < 8; nj++)
                    mma_bf16(d[mi][nj], aH[mi], bL[nj]);
#pragma unroll
            for (int mi = 0; mi < 4; mi++)
#pragma unroll
                for (int nj = 0; nj < 8; nj++)
                    mma_bf16(d[mi][nj], aL[mi], bH[nj]);
        }

        __syncthreads();   // all warps done reading before overwrite
        if (it + 2 < KITERS)
            load_stage(stg, mBase, nBase, (it + 2) * BK, tid);
        cp_commit();       // empty groups keep wait_group counting valid
    }

#pragma unroll
    for (int mi = 0; mi < 4; mi++) {
        const size_t grow = mBase + wm * 64 + mi * 16 + (lane >> 2);
#pragma unroll
        for (int nj = 0; nj < 8; nj++) {
            const size_t gcol = nBase + wn * 64 + nj * 8 + (lane & 3) * 2;
            *reinterpret_cast<float2*>(out + grow * D_DIM + gcol) =
                make_float2(d[mi][nj][0], d[mi][nj][1]);
            *reinterpret_cast<float2*>(out + (grow + 8) * D_DIM + gcol) =
                make_float2(d[mi][nj][2], d[mi][nj][3]);
        }
    }
}

// ---------------------------------------------------------------------------
// Launch
// ---------------------------------------------------------------------------
extern "C" void kernel_launch(void* const* d_in, const int* in_sizes, int n_in,
                              void* d_out, int out_size) {
    const float* x     = (const float*)d_in[0];
    const float* W     = (const float*)d_in[1];
    const float* lA    = (const float*)d_in[2];
    const float* lB    = (const float*)d_in[3];
    const float* sigma = (const float*)d_in[4];
    float* out = (float*)d_out;
    (void)in_sizes; (void)n_in; (void)out_size;

    dim3 gF(D_DIM / 1024, D_DIM);
    fold_w_kernel<<<gF, 256>>>(W, lA, lB, sigma);

    const size_t nx4 = (size_t)M_DIM * D_DIM / 4;
    split_x_kernel<<<(unsigned)(nx4 / 256), 256>>>(x);

    cudaFuncSetAttribute(gemm_mma_kernel,
                         cudaFuncAttributeMaxDynamicSharedMemorySize, SMEM_BYTES);
    dim3 gG(D_DIM / BN, M_DIM / BM);
    gemm_mma_kernel<<<gG, 256, SMEM_BYTES>>>(out);
}

// round 5
// speedup vs baseline: 5.2944x; 1.4979x over previous
#include <cuda_runtime.h>
#include <cuda_fp16.h>
#include <cstdint>

// AdaLoRALinear: out[8192,4096] = x[8192,4096] @ (W + (B*sigma_m)@A)^T
// fp16x2 scheme: x = xh + xl (both fp16), W single fp16.
// out = xh*W + xl*W  (2 MMA products; W quant bound 2^-11 dominates error).

#define D_DIM 4096
#define R_DIM 16
#define M_DIM 8192
#define SCALING 1.0f
#define THRESH  0.01f

#define BM 128
#define BN 256
#define BK 64                  // 64 fp16 = 128B row (SW128 atom)
#define KITERS (D_DIM / BK)    // 64

__device__ __half g_xh[(size_t)M_DIM * D_DIM];
__device__ __half g_xl[(size_t)M_DIM * D_DIM];
__device__ __half g_w16[(size_t)D_DIM * D_DIM];

// ---------------------------------------------------------------------------
// helpers
// ---------------------------------------------------------------------------
__device__ __forceinline__ uint32_t smem_u32(const void* p) {
    uint32_t a;
    asm("{ .reg .u64 t; cvta.to.shared.u64 t, %1; cvt.u32.u64 %0, t; }"
        : "=r"(a) : "l"(p));
    return a;
}
__device__ __forceinline__ uint32_t swz128(uint32_t off) {
    return off ^ ((off >> 3) & 0x70);
}
__device__ __forceinline__ void cp16(uint32_t smem, const void* g) {
    asm volatile("cp.async.cg.shared.global [%0], [%1], 16;\n"
                 :: "r"(smem), "l"(g) : "memory");
}
__device__ __forceinline__ void cp_commit() {
    asm volatile("cp.async.commit_group;\n" ::: "memory");
}
__device__ __forceinline__ void cp_wait1() {
    asm volatile("cp.async.wait_group 1;\n" ::: "memory");
}
__device__ __forceinline__ void ldsm4(uint32_t* r, uint32_t addr) {
    asm volatile("ldmatrix.sync.aligned.m8n8.x4.shared.b16 {%0,%1,%2,%3}, [%4];"
                 : "=r"(r[0]), "=r"(r[1]), "=r"(r[2]), "=r"(r[3]) : "r"(addr));
}
__device__ __forceinline__ void mma_f16(float* d, const uint32_t* a,
                                        const uint32_t* b) {
    asm volatile(
        "mma.sync.aligned.m16n8k16.row.col.f32.f16.f16.f32 "
        "{%0,%1,%2,%3}, {%4,%5,%6,%7}, {%8,%9}, {%0,%1,%2,%3};"
        : "+f"(d[0]), "+f"(d[1]), "+f"(d[2]), "+f"(d[3])
        : "r"(a[0]), "r"(a[1]), "r"(a[2]), "r"(a[3]), "r"(b[0]), "r"(b[1]));
}

// ---------------------------------------------------------------------------
// Prep 1: W' = W + (B*sigma_m)@A -> single fp16
// ---------------------------------------------------------------------------
__global__ void fold_w_kernel(const float* __restrict__ W,
                              const float* __restrict__ A,
                              const float* __restrict__ B,
                              const float* __restrict__ sigma) {
    __shared__ float bsig[R_DIM];
    const int o = blockIdx.y;
    const int i = (blockIdx.x * blockDim.x + threadIdx.x) * 4;
    if (threadIdx.x < R_DIM) {
        float s = sigma[threadIdx.x];
        s = (fabsf(s) >= THRESH) ? s : 0.0f;
        bsig[threadIdx.x] = B[o * R_DIM + threadIdx.x] * s * SCALING;
    }
    __syncthreads();

    const size_t idx = (size_t)o * D_DIM + i;
    float4 w4 = *reinterpret_cast<const float4*>(W + idx);
    float acc[4] = {w4.x, w4.y, w4.z, w4.w};
#pragma unroll
    for (int r = 0; r < R_DIM; r++) {
        const float4 a4 = *reinterpret_cast<const float4*>(A + (size_t)r * D_DIM + i);
        const float b = bsig[r];
        acc[0] = fmaf(b, a4.x, acc[0]);
        acc[1] = fmaf(b, a4.y, acc[1]);
        acc[2] = fmaf(b, a4.z, acc[2]);
        acc[3] = fmaf(b, a4.w, acc[3]);
    }
    __half h[4];
#pragma unroll
    for (int j = 0; j < 4; j++) h[j] = __float2half_rn(acc[j]);
    *reinterpret_cast<uint2*>(&g_w16[idx]) = *reinterpret_cast<uint2*>(h);
}

// ---------------------------------------------------------------------------
// Prep 2: x -> fp16 hi + fp16 residual
// ---------------------------------------------------------------------------
__global__ void split_x_kernel(const float* __restrict__ x) {
    const size_t idx = (size_t)blockIdx.x * blockDim.x + threadIdx.x;
    const float4 v = reinterpret_cast<const float4*>(x)[idx];
    float vv[4] = {v.x, v.y, v.z, v.w};
    __half h[4], l[4];
#pragma unroll
    for (int j = 0; j < 4; j++) {
        h[j] = __float2half_rn(vv[j]);
        l[j] = __float2half_rn(vv[j] - __half2float(h[j]));
    }
    *reinterpret_cast<uint2*>(&g_xh[idx * 4]) = *reinterpret_cast<uint2*>(h);
    *reinterpret_cast<uint2*>(&g_xl[idx * 4]) = *reinterpret_cast<uint2*>(l);
}

// ---------------------------------------------------------------------------
// GEMM: CTA 128x256, 8 warps (2m x 4n), warp 64x64, BK=64, 3-stage pipeline.
// Stage (64 KB): Ah(16K) Al(16K) B(32K), SW128 rows. One barrier per iter.
// ---------------------------------------------------------------------------
#define STAGE_BYTES 65536
#define OFF_AH 0
#define OFF_AL 16384
#define OFF_B  32768
#define SMEM_BYTES (3 * STAGE_BYTES + 128)

__device__ __forceinline__ void load_stage(uint32_t base, size_t mBase,
                                           size_t nBase, int kt, int tid) {
#pragma unroll
    for (int i = 0; i < 4; i++) {   // A hi/lo: 128 rows x 8 units each
        const int u = tid + 256 * i;
        const int row = u >> 3, kc = u & 7;
        const uint32_t so = swz128(row * 128 + kc * 16);
        const size_t ga = ((mBase + row) << 12) + kt + kc * 8;
        cp16(base + OFF_AH + so, g_xh + ga);
        cp16(base + OFF_AL + so, g_xl + ga);
    }
#pragma unroll
    for (int i = 0; i < 8; i++) {   // B: 256 rows x 8 units
        const int u = tid + 256 * i;
        const int row = u >> 3, kc = u & 7;
        const uint32_t so = swz128(row * 128 + kc * 16);
        const size_t gb = ((nBase + row) << 12) + kt + kc * 8;
        cp16(base + OFF_B + so, g_w16 + gb);
    }
}

__global__ __launch_bounds__(256, 1)
void gemm_mma_kernel(float* __restrict__ out) {
    extern __shared__ char smem_raw[];
    const uint32_t tiles = (smem_u32(smem_raw) + 127u) & ~127u;

    const int tid = threadIdx.x;
    const int lane = tid & 31;
    const int w = tid >> 5;
    const int wm = w >> 2;        // 0..1 -> M half
    const int wn = w & 3;         // 0..3 -> N quarter
    const size_t mBase = (size_t)blockIdx.y * BM;
    const size_t nBase = (size_t)blockIdx.x * BN;

    float d[4][8][4];
#pragma unroll
    for (int i = 0; i < 4; i++)
#pragma unroll
        for (int j = 0; j < 8; j++)
#pragma unroll
            for (int k = 0; k < 4; k++) d[i][j][k] = 0.0f;

    const int arow = wm * 64 + (lane & 15);
    const int acol = (lane >> 4);
    const int brow = wn * 64 + (lane & 7) + ((lane >> 4) << 3);
    const int bcol = ((lane >> 3) & 1);

    load_stage(tiles, mBase, nBase, 0, tid);
    cp_commit();
    load_stage(tiles + STAGE_BYTES, mBase, nBase, BK, tid);
    cp_commit();

    for (int it = 0; it < KITERS; it++) {
        const uint32_t stg = tiles + (it % 3) * STAGE_BYTES;

        cp_wait1();          // oldest pending group (stage it) complete
        __syncthreads();

#pragma unroll
        for (int k16 = 0; k16 < 4; k16++) {
            uint32_t aH[4][4], aL[4][4], b[8][2];
#pragma unroll
            for (int mi = 0; mi < 4; mi++) {
                const uint32_t off =
                    swz128((arow + mi * 16) * 128 + (acol + k16 * 2) * 16);
                ldsm4(aH[mi], stg + OFF_AH + off);
                ldsm4(aL[mi], stg + OFF_AL + off);
            }
#pragma unroll
            for (int j = 0; j < 4; j++) {
                uint32_t q[4];
                const uint32_t off =
                    swz128((brow + j * 16) * 128 + (bcol + k16 * 2) * 16);
                ldsm4(q, stg + OFF_B + off);
                b[2 * j][0] = q[0]; b[2 * j][1] = q[1];
                b[2 * j + 1][0] = q[2]; b[2 * j + 1][1] = q[3];
            }
#pragma unroll
            for (int mi = 0; mi < 4; mi++)
#pragma unroll
                for (int nj = 0; nj < 8; nj++)
                    mma_f16(d[mi][nj], aH[mi], b[nj]);
#pragma unroll
            for (int mi = 0; mi < 4; mi++)
#pragma unroll
                for (int nj = 0; nj < 8; nj++)
                    mma_f16(d[mi][nj], aL[mi], b[nj]);
        }

        // Load into stage (it+2)%3 == (it-1)%3: drained — every warp passed
        // this iteration's barrier, so all finished computing stage it-1.
        if (it + 2 < KITERS)
            load_stage(tiles + ((it + 2) % 3) * STAGE_BYTES,
                       mBase, nBase, (it + 2) * BK, tid);
        cp_commit();         // empty groups at tail keep wait counts valid
    }

#pragma unroll
    for (int mi = 0; mi < 4; mi++) {
        const size_t grow = mBase + wm * 64 + mi * 16 + (lane >> 2);
#pragma unroll
        for (int nj = 0; nj < 8; nj++) {
            const size_t gcol = nBase + wn * 64 + nj * 8 + (lane & 3) * 2;
            *reinterpret_cast<float2*>(out + grow * D_DIM + gcol) =
                make_float2(d[mi][nj][0], d[mi][nj][1]);
            *reinterpret_cast<float2*>(out + (grow + 8) * D_DIM + gcol) =
                make_float2(d[mi][nj][2], d[mi][nj][3]);
        }
    }
}

// ---------------------------------------------------------------------------
// Launch
// ---------------------------------------------------------------------------
extern "C" void kernel_launch(void* const* d_in, const int* in_sizes, int n_in,
                              void* d_out, int out_size) {
    const float* x     = (const float*)d_in[0];
    const float* W     = (const float*)d_in[1];
    const float* lA    = (const float*)d_in[2];
    const float* lB    = (const float*)d_in[3];
    const float* sigma = (const float*)d_in[4];
    float* out = (float*)d_out;
    (void)in_sizes; (void)n_in; (void)out_size;

    dim3 gF(D_DIM / 1024, D_DIM);
    fold_w_kernel<<<gF, 256>>>(W, lA, lB, sigma);

    const size_t nx4 = (size_t)M_DIM * D_DIM / 4;
    split_x_kernel<<<(unsigned)(nx4 / 256), 256>>>(x);

    cudaFuncSetAttribute(gemm_mma_kernel,
                         cudaFuncAttributeMaxDynamicSharedMemorySize, SMEM_BYTES);
    dim3 gG(D_DIM / BN, M_DIM / BM);
    gemm_mma_kernel<<<gG, 256, SMEM_BYTES>>>(out);
}

// round 6
// speedup vs baseline: 8.8396x; 1.6696x over previous
#include <cuda_runtime.h>
#include <cuda_fp16.h>
#include <cstdint>

// AdaLoRALinear: out[8192,4096] = x[8192,4096] @ (W + (B*sigma_m)@A)^T
// Single-pass fp16 GEMM on mma.sync (measured error budget allows it:
// fp16x2 gave 2.08e-4 = W-quant alone; adding x-quant RMS -> ~2.9e-4 < 1e-3).

#define D_DIM 4096
#define R_DIM 16
#define M_DIM 8192
#define SCALING 1.0f
#define THRESH  0.01f

#define BM 128
#define BN 256
#define BK 64                  // 64 fp16 = 128B row (SW128 atom)
#define KITERS (D_DIM / BK)    // 64

__device__ __half g_x16[(size_t)M_DIM * D_DIM];
__device__ __half g_w16[(size_t)D_DIM * D_DIM];

// ---------------------------------------------------------------------------
// helpers
// ---------------------------------------------------------------------------
__device__ __forceinline__ uint32_t smem_u32(const void* p) {
    uint32_t a;
    asm("{ .reg .u64 t; cvta.to.shared.u64 t, %1; cvt.u32.u64 %0, t; }"
        : "=r"(a) : "l"(p));
    return a;
}
__device__ __forceinline__ uint32_t swz128(uint32_t off) {
    return off ^ ((off >> 3) & 0x70);
}
__device__ __forceinline__ void cp16(uint32_t smem, const void* g) {
    asm volatile("cp.async.cg.shared.global [%0], [%1], 16;\n"
                 :: "r"(smem), "l"(g) : "memory");
}
__device__ __forceinline__ void cp_commit() {
    asm volatile("cp.async.commit_group;\n" ::: "memory");
}
__device__ __forceinline__ void cp_wait1() {
    asm volatile("cp.async.wait_group 1;\n" ::: "memory");
}
__device__ __forceinline__ void ldsm4(uint32_t* r, uint32_t addr) {
    asm volatile("ldmatrix.sync.aligned.m8n8.x4.shared.b16 {%0,%1,%2,%3}, [%4];"
                 : "=r"(r[0]), "=r"(r[1]), "=r"(r[2]), "=r"(r[3]) : "r"(addr));
}
__device__ __forceinline__ void mma_f16(float* d, const uint32_t* a,
                                        const uint32_t* b) {
    asm volatile(
        "mma.sync.aligned.m16n8k16.row.col.f32.f16.f16.f32 "
        "{%0,%1,%2,%3}, {%4,%5,%6,%7}, {%8,%9}, {%0,%1,%2,%3};"
        : "+f"(d[0]), "+f"(d[1]), "+f"(d[2]), "+f"(d[3])
        : "r"(a[0]), "r"(a[1]), "r"(a[2]), "r"(a[3]), "r"(b[0]), "r"(b[1]));
}

// ---------------------------------------------------------------------------
// Prep 1: W' = W + (B*sigma_m)@A -> fp16
// ---------------------------------------------------------------------------
__global__ void fold_w_kernel(const float* __restrict__ W,
                              const float* __restrict__ A,
                              const float* __restrict__ B,
                              const float* __restrict__ sigma) {
    __shared__ float bsig[R_DIM];
    const int o = blockIdx.y;
    const int i = (blockIdx.x * blockDim.x + threadIdx.x) * 4;
    if (threadIdx.x < R_DIM) {
        float s = sigma[threadIdx.x];
        s = (fabsf(s) >= THRESH) ? s : 0.0f;
        bsig[threadIdx.x] = B[o * R_DIM + threadIdx.x] * s * SCALING;
    }
    __syncthreads();

    const size_t idx = (size_t)o * D_DIM + i;
    float4 w4 = *reinterpret_cast<const float4*>(W + idx);
    float acc[4] = {w4.x, w4.y, w4.z, w4.w};
#pragma unroll
    for (int r = 0; r < R_DIM; r++) {
        const float4 a4 = *reinterpret_cast<const float4*>(A + (size_t)r * D_DIM + i);
        const float b = bsig[r];
        acc[0] = fmaf(b, a4.x, acc[0]);
        acc[1] = fmaf(b, a4.y, acc[1]);
        acc[2] = fmaf(b, a4.z, acc[2]);
        acc[3] = fmaf(b, a4.w, acc[3]);
    }
    __half h[4];
#pragma unroll
    for (int j = 0; j < 4; j++) h[j] = __float2half_rn(acc[j]);
    *reinterpret_cast<uint2*>(&g_w16[idx]) = *reinterpret_cast<uint2*>(h);
}

// ---------------------------------------------------------------------------
// Prep 2: x -> fp16
// ---------------------------------------------------------------------------
__global__ void conv_x_kernel(const float* __restrict__ x) {
    const size_t idx = (size_t)blockIdx.x * blockDim.x + threadIdx.x;
    const float4 v = reinterpret_cast<const float4*>(x)[idx];
    __half h[4] = {__float2half_rn(v.x), __float2half_rn(v.y),
                   __float2half_rn(v.z), __float2half_rn(v.w)};
    *reinterpret_cast<uint2*>(&g_x16[idx * 4]) = *reinterpret_cast<uint2*>(h);
}

// ---------------------------------------------------------------------------
// GEMM: CTA 128x256, 8 warps (2m x 4n), warp 64x64, BK=64, 3-stage pipeline.
// Stage (48 KB): A(16K) B(32K), SW128 rows. One barrier per iter; loads issue
// right after the barrier (stage (it+2)%3 is drained there) to hide latency.
// ---------------------------------------------------------------------------
#define STAGE_BYTES 49152
#define OFF_A 0
#define OFF_B 16384
#define SMEM_BYTES (3 * STAGE_BYTES + 128)

__device__ __forceinline__ void load_stage(uint32_t base, size_t mBase,
                                           size_t nBase, int kt, int tid) {
#pragma unroll
    for (int i = 0; i < 4; i++) {   // A: 128 rows x 8 units
        const int u = tid + 256 * i;
        const int row = u >> 3, kc = u & 7;
        const uint32_t so = swz128(row * 128 + kc * 16);
        cp16(base + OFF_A + so, g_x16 + ((mBase + row) << 12) + kt + kc * 8);
    }
#pragma unroll
    for (int i = 0; i < 8; i++) {   // B: 256 rows x 8 units
        const int u = tid + 256 * i;
        const int row = u >> 3, kc = u & 7;
        const uint32_t so = swz128(row * 128 + kc * 16);
        cp16(base + OFF_B + so, g_w16 + ((nBase + row) << 12) + kt + kc * 8);
    }
}

__global__ __launch_bounds__(256, 1)
void gemm_mma_kernel(float* __restrict__ out) {
    extern __shared__ char smem_raw[];
    const uint32_t tiles = (smem_u32(smem_raw) + 127u) & ~127u;

    const int tid = threadIdx.x;
    const int lane = tid & 31;
    const int w = tid >> 5;
    const int wm = w >> 2;        // 0..1 -> M half
    const int wn = w & 3;         // 0..3 -> N quarter
    const size_t mBase = (size_t)blockIdx.y * BM;
    const size_t nBase = (size_t)blockIdx.x * BN;

    float d[4][8][4];
#pragma unroll
    for (int i = 0; i < 4; i++)
#pragma unroll
        for (int j = 0; j < 8; j++)
#pragma unroll
            for (int k = 0; k < 4; k++) d[i][j][k] = 0.0f;

    const int arow = wm * 64 + (lane & 15);
    const int acol = (lane >> 4);
    const int brow = wn * 64 + (lane & 7) + ((lane >> 4) << 3);
    const int bcol = ((lane >> 3) & 1);

    load_stage(tiles, mBase, nBase, 0, tid);
    cp_commit();
    load_stage(tiles + STAGE_BYTES, mBase, nBase, BK, tid);
    cp_commit();

    for (int it = 0; it < KITERS; it++) {
        const uint32_t stg = tiles + (it % 3) * STAGE_BYTES;

        cp_wait1();          // oldest pending group (stage it) complete
        __syncthreads();

        // Issue next loads first: stage (it+2)%3 == (it-1)%3 is drained —
        // every warp passed this barrier, so all finished computing it-1.
        if (it + 2 < KITERS)
            load_stage(tiles + ((it + 2) % 3) * STAGE_BYTES,
                       mBase, nBase, (it + 2) * BK, tid);
        cp_commit();         // empty groups at tail keep wait counts valid

#pragma unroll
        for (int k16 = 0; k16 < 4; k16++) {
            uint32_t a[4][4], b[8][2];
#pragma unroll
            for (int mi = 0; mi < 4; mi++) {
                const uint32_t off =
                    swz128((arow + mi * 16) * 128 + (acol + k16 * 2) * 16);
                ldsm4(a[mi], stg + OFF_A + off);
            }
#pragma unroll
            for (int j = 0; j < 4; j++) {
                uint32_t q[4];
                const uint32_t off =
                    swz128((brow + j * 16) * 128 + (bcol + k16 * 2) * 16);
                ldsm4(q, stg + OFF_B + off);
                b[2 * j][0] = q[0]; b[2 * j][1] = q[1];
                b[2 * j + 1][0] = q[2]; b[2 * j + 1][1] = q[3];
            }
#pragma unroll
            for (int mi = 0; mi < 4; mi++)
#pragma unroll
                for (int nj = 0; nj < 8; nj++)
                    mma_f16(d[mi][nj], a[mi], b[nj]);
        }
    }

#pragma unroll
    for (int mi = 0; mi < 4; mi++) {
        const size_t grow = mBase + wm * 64 + mi * 16 + (lane >> 2);
#pragma unroll
        for (int nj = 0; nj < 8; nj++) {
            const size_t gcol = nBase + wn * 64 + nj * 8 + (lane & 3) * 2;
            *reinterpret_cast<float2*>(out + grow * D_DIM + gcol) =
                make_float2(d[mi][nj][0], d[mi][nj][1]);
            *reinterpret_cast<float2*>(out + (grow + 8) * D_DIM + gcol) =
                make_float2(d[mi][nj][2], d[mi][nj][3]);
        }
    }
}

// ---------------------------------------------------------------------------
// Launch
// ---------------------------------------------------------------------------
extern "C" void kernel_launch(void* const* d_in, const int* in_sizes, int n_in,
                              void* d_out, int out_size) {
    const float* x     = (const float*)d_in[0];
    const float* W     = (const float*)d_in[1];
    const float* lA    = (const float*)d_in[2];
    const float* lB    = (const float*)d_in[3];
    const float* sigma = (const float*)d_in[4];
    float* out = (float*)d_out;
    (void)in_sizes; (void)n_in; (void)out_size;

    dim3 gF(D_DIM / 1024, D_DIM);
    fold_w_kernel<<<gF, 256>>>(W, lA, lB, sigma);

    const size_t nx4 = (size_t)M_DIM * D_DIM / 4;
    conv_x_kernel<<<(unsigned)(nx4 / 256), 256>>>(x);

    cudaFuncSetAttribute(gemm_mma_kernel,
                         cudaFuncAttributeMaxDynamicSharedMemorySize, SMEM_BYTES);
    dim3 gG(D_DIM / BN, M_DIM / BM);
    gemm_mma_kernel<<<gG, 256, SMEM_BYTES>>>(out);
}